// round 9
// baseline (speedup 1.0000x reference)
#include <cuda_runtime.h>
#include <math.h>
#include <stdint.h>

#define BT 2048
#define HS 1024
#define HT 2048
#define VV 32000

#define BM 128
#define BN 128
#define BKK 16
#define SSTRIDE 20   // floats per smem row; 20*r mod 32 spreads banks conflict-free

#define LOG2E 1.4426950408889634f
#define LN2F  0.6931471805599453f

// Scratch (device-global: allocation-free per harness rules)
__device__ float g_slog[(size_t)BT * VV];   // student logits
__device__ float g_tlog[(size_t)BT * VV];   // teacher logits
__device__ float g_sexp[(size_t)BT * VV];   // exp(student logits)
__device__ float g_texp[(size_t)BT * VV];   // exp(teacher logits)
__device__ float g_Zs[BT];
__device__ float g_Zt[BT];
__device__ float g_pt[BT];

__device__ __forceinline__ uint32_t f2tf32(float f) {
    uint32_t u;
    asm("cvt.rna.tf32.f32 %0, %1;" : "=r"(u) : "f"(f));
    return u;
}
__device__ __forceinline__ void mma_tf32(float* c, const uint32_t* a,
                                         const uint32_t* b) {
    asm volatile(
        "mma.sync.aligned.m16n8k8.row.col.f32.tf32.tf32.f32 "
        "{%0,%1,%2,%3}, {%4,%5,%6,%7}, {%8,%9}, {%0,%1,%2,%3};"
        : "+f"(c[0]), "+f"(c[1]), "+f"(c[2]), "+f"(c[3])
        : "r"(a[0]), "r"(a[1]), "r"(a[2]), "r"(a[3]), "r"(b[0]), "r"(b[1]));
}
__device__ __forceinline__ void cpa16(uint32_t s, const void* g) {
    asm volatile("cp.async.cg.shared.global [%0], [%1], 16;" :: "r"(s), "l"(g));
}
__device__ __forceinline__ uint32_t smem_u32(const void* p) {
    uint32_t a;
    asm("{ .reg .u64 t; cvta.to.shared.u64 t, %1; cvt.u32.u64 %0, t; }"
        : "=r"(a) : "l"(p));
    return a;
}

// ---------------------------------------------------------------------------
__global__ void zeroZ(float* __restrict__ zs, float* __restrict__ zt) {
    int i = blockIdx.x * 256 + threadIdx.x;
    if (i < BT) { zs[i] = 0.0f; zt[i] = 0.0f; }
}

// ---------------------------------------------------------------------------
// NT GEMM via mma.sync tf32 + fused exp epilogue:
//   C[m][n] = sum_k A[m][k] * B[n][k];  E = exp(C);  Z[m] += row-sum(E tile)
// BM=128, BN=128, BK=16, 256 threads (8 warps, 2m x 4n), warp tile 64x32.
// ---------------------------------------------------------------------------
__global__ __launch_bounds__(256) void gemm_mma(const float* __restrict__ A,
                                                const float* __restrict__ B,
                                                float* __restrict__ C,
                                                float* __restrict__ E,
                                                float* __restrict__ Z,
                                                int K, int N) {
    __shared__ float sA[2][BM * SSTRIDE];
    __shared__ float sB[2][BN * SSTRIDE];

    const int tid = threadIdx.x;
    const int lane = tid & 31;
    const int wid = tid >> 5;
    const int wm = (wid & 1) * 64;
    const int wn = (wid >> 1) * 32;
    const int g = lane >> 2;
    const int tg = lane & 3;

    const int bm = blockIdx.x * BM;
    const int bn = blockIdx.y * BN;

    const int lr = tid >> 2;
    const int lc = tid & 3;
    const uint32_t sAu = smem_u32(sA);
    const uint32_t sBu = smem_u32(sB);

    auto load_tile = [&](int buf, int kb) {
        const float* Ag = A + (size_t)bm * K + kb * BKK + lc * 4;
        const float* Bg = B + (size_t)bn * K + kb * BKK + lc * 4;
        uint32_t dA = sAu + (uint32_t)buf * BM * SSTRIDE * 4;
        uint32_t dB = sBu + (uint32_t)buf * BN * SSTRIDE * 4;
        cpa16(dA + (lr * SSTRIDE + lc * 4) * 4, Ag + (size_t)lr * K);
        cpa16(dA + ((lr + 64) * SSTRIDE + lc * 4) * 4, Ag + (size_t)(lr + 64) * K);
        cpa16(dB + (lr * SSTRIDE + lc * 4) * 4, Bg + (size_t)lr * K);
        cpa16(dB + ((lr + 64) * SSTRIDE + lc * 4) * 4, Bg + (size_t)(lr + 64) * K);
        asm volatile("cp.async.commit_group;" ::: "memory");
    };

    float acc[4][4][4];
#pragma unroll
    for (int i = 0; i < 4; i++)
#pragma unroll
        for (int j = 0; j < 4; j++)
#pragma unroll
            for (int c = 0; c < 4; c++) acc[i][j][c] = 0.0f;

    const int KB = K / BKK;
    load_tile(0, 0);

    for (int kb = 0; kb < KB; kb++) {
        const int buf = kb & 1;
        if (kb + 1 < KB) {
            load_tile(buf ^ 1, kb + 1);
            asm volatile("cp.async.wait_group 1;" ::: "memory");
        } else {
            asm volatile("cp.async.wait_group 0;" ::: "memory");
        }
        __syncthreads();

        const float* tA = sA[buf];
        const float* tB = sB[buf];
#pragma unroll
        for (int ks = 0; ks < 2; ks++) {
            const int k0 = ks * 8;
            uint32_t af[4][4], bf[4][2];
#pragma unroll
            for (int i = 0; i < 4; i++) {
                int r = wm + i * 16 + g;
                af[i][0] = f2tf32(tA[r * SSTRIDE + k0 + tg]);
                af[i][1] = f2tf32(tA[(r + 8) * SSTRIDE + k0 + tg]);
                af[i][2] = f2tf32(tA[r * SSTRIDE + k0 + tg + 4]);
                af[i][3] = f2tf32(tA[(r + 8) * SSTRIDE + k0 + tg + 4]);
            }
#pragma unroll
            for (int j = 0; j < 4; j++) {
                int n = wn + j * 8 + g;
                bf[j][0] = f2tf32(tB[n * SSTRIDE + k0 + tg]);
                bf[j][1] = f2tf32(tB[n * SSTRIDE + k0 + tg + 4]);
            }
#pragma unroll
            for (int i = 0; i < 4; i++)
#pragma unroll
                for (int j = 0; j < 4; j++) mma_tf32(acc[i][j], af[i], bf[j]);
        }
        __syncthreads();
    }

    // epilogue: store logits + exp(logits); row-sum exps -> atomicAdd Z[row]
#pragma unroll
    for (int i = 0; i < 4; i++) {
        const int row = bm + wm + i * 16 + g;
        float rs0 = 0.0f, rs1 = 0.0f;
#pragma unroll
        for (int j = 0; j < 4; j++) {
            const int col = bn + wn + j * 8 + 2 * tg;
            float c00 = acc[i][j][0], c01 = acc[i][j][1];
            float c10 = acc[i][j][2], c11 = acc[i][j][3];
            float e00 = __expf(c00), e01 = __expf(c01);
            float e10 = __expf(c10), e11 = __expf(c11);
            rs0 += e00 + e01;
            rs1 += e10 + e11;
            *(float2*)(C + (size_t)row * N + col) = make_float2(c00, c01);
            *(float2*)(C + (size_t)(row + 8) * N + col) = make_float2(c10, c11);
            *(float2*)(E + (size_t)row * N + col) = make_float2(e00, e01);
            *(float2*)(E + (size_t)(row + 8) * N + col) = make_float2(e10, e11);
        }
        // reduce over the 4 lanes (tg) that share this row
        rs0 += __shfl_xor_sync(0xffffffffu, rs0, 1);
        rs0 += __shfl_xor_sync(0xffffffffu, rs0, 2);
        rs1 += __shfl_xor_sync(0xffffffffu, rs1, 1);
        rs1 += __shfl_xor_sync(0xffffffffu, rs1, 2);
        if (tg == 0) {
            atomicAdd(&Z[row], rs0);
            atomicAdd(&Z[row + 8], rs1);
        }
    }
}

// ---------------------------------------------------------------------------
// Single-pass JSD per row. 1 MUFU (lg2) per vocab element.
// per-token = 0.5*ln2*( sum p*lp2 + sum q*lq2 - sum (p+q)*log2(p+q) ) + ln2
// where lp2 = t*log2e - log2(Zt), lq2 = s*log2e - log2(Zs).
// ---------------------------------------------------------------------------
__global__ __launch_bounds__(256) void rowjsd(const float* __restrict__ S,
                                              const float* __restrict__ T,
                                              const float* __restrict__ ES,
                                              const float* __restrict__ ET,
                                              const float* __restrict__ Zs,
                                              const float* __restrict__ Zt,
                                              float* __restrict__ pt) {
    const int row = blockIdx.x;
    const int tid = threadIdx.x;
    const size_t off = (size_t)row * VV;
    const float4* s4 = (const float4*)(S + off);
    const float4* t4 = (const float4*)(T + off);
    const float4* es4 = (const float4*)(ES + off);
    const float4* et4 = (const float4*)(ET + off);

    // per-row constants in fp64 (once; removes systematic row bias)
    const double zs = (double)Zs[row];
    const double zt = (double)Zt[row];
    const float invZs = (float)(1.0 / zs);
    const float invZt = (float)(1.0 / zt);
    const float cs = (float)(-log2(zs));
    const float ct = (float)(-log2(zt));

    float a1 = 0.0f, a2 = 0.0f, a3 = 0.0f;
    const int N4 = VV / 4;  // 8000
    for (int i = tid; i < N4; i += 256) {
        float4 sv = s4[i];
        float4 tv = t4[i];
        float4 ev = es4[i];
        float4 fv = et4[i];
#pragma unroll
        for (int j = 0; j < 4; j++) {
            float q = ((&ev.x)[j]) * invZs;
            float p = ((&fv.x)[j]) * invZt;
            float lq2 = fmaf((&sv.x)[j], LOG2E, cs);
            float lp2 = fmaf((&tv.x)[j], LOG2E, ct);
            float sum = p + q;
            float L2 = __log2f(sum);
            a1 = fmaf(p, lp2, a1);
            a2 = fmaf(q, lq2, a2);
            a3 = fmaf(sum, L2, a3);
        }
    }

    __shared__ float r0[256];
    float a = a1 + a2 - a3;
    r0[tid] = a;
    __syncthreads();
    for (int o = 128; o > 0; o >>= 1) {
        if (tid < o) r0[tid] += r0[tid + o];
        __syncthreads();
    }
    if (tid == 0) pt[row] = 0.5f * LN2F * r0[0] + LN2F;
}

// ---------------------------------------------------------------------------
__global__ __launch_bounds__(256) void finalize(const float* __restrict__ pt,
                                                const int* __restrict__ label,
                                                float* __restrict__ out) {
    const int tid = threadIdx.x;
    float sum = 0.0f;
    int cnt = 0;
    for (int i = tid; i < BT; i += 256) {
        if (label[i] != -100) { sum += pt[i]; cnt++; }
    }
    __shared__ float rs[256];
    __shared__ int rc[256];
    rs[tid] = sum; rc[tid] = cnt;
    __syncthreads();
    for (int o = 128; o > 0; o >>= 1) {
        if (tid < o) { rs[tid] += rs[tid + o]; rc[tid] += rc[tid + o]; }
        __syncthreads();
    }
    if (tid == 0) {
        int n = rc[0] > 1 ? rc[0] : 1;
        out[0] = rs[0] / (float)n;
    }
}

// ---------------------------------------------------------------------------
extern "C" void kernel_launch(void* const* d_in, const int* in_sizes, int n_in,
                              void* d_out, int out_size) {
    const float* si = (const float*)d_in[0];   // student_input  [BT, HS]
    const float* sw = (const float*)d_in[1];   // student_weight [V, HS]
    const float* ti = (const float*)d_in[2];   // teacher_input  [BT, HT]
    const float* tw = (const float*)d_in[3];   // teacher_weight [V, HT]
    const int*   lb = (const int*)d_in[4];     // label [BT]

    float *slog, *tlog, *sexp, *texp, *zs, *zt, *ptv;
    cudaGetSymbolAddress((void**)&slog, g_slog);
    cudaGetSymbolAddress((void**)&tlog, g_tlog);
    cudaGetSymbolAddress((void**)&sexp, g_sexp);
    cudaGetSymbolAddress((void**)&texp, g_texp);
    cudaGetSymbolAddress((void**)&zs, g_Zs);
    cudaGetSymbolAddress((void**)&zt, g_Zt);
    cudaGetSymbolAddress((void**)&ptv, g_pt);

    zeroZ<<<(BT + 255) / 256, 256>>>(zs, zt);

    dim3 grid(BT / BM, VV / BN);  // (16, 250): m fast -> B tiles shared in L2
    gemm_mma<<<grid, 256>>>(si, sw, slog, sexp, zs, HS, VV);
    gemm_mma<<<grid, 256>>>(ti, tw, tlog, texp, zt, HT, VV);
    rowjsd<<<BT, 256>>>(slog, tlog, sexp, texp, zs, zt, ptv);
    finalize<<<1, 256>>>(ptv, lb, (float*)d_out);
}